// round 1
// baseline (speedup 1.0000x reference)
#include <cuda_runtime.h>
#include <math.h>

// Problem constants
#define BATCH   32
#define SEQ     1024
#define INDIM   1024
#define DDIM    1024
#define MLPDIM  2048
#define NCLS    10
#define BSROWS  (BATCH * SEQ)     // 32768 rows
#define KCAT    (2 * INDIM)       // 2048 (x ; xprev concatenated)

// -------- scratch (device globals; no allocation allowed) --------
__device__ float g_F[(size_t)BSROWS * DDIM];   // f = sigmoid(f_pre)  [B*S, D]  (128 MB)
__device__ float g_c[BATCH * DDIM];            // c_last
__device__ float g_h[BATCH * DDIM];            // h_last = c_last * o_last
__device__ float g_q0[BATCH * MLPDIM];
__device__ float g_q1[BATCH * MLPDIM];

__device__ __forceinline__ float sigmoidf_(float v) {
    return 1.0f / (1.0f + expf(-v));
}

// ============================================================================
// Kernel 1: f_pre GEMM.  C[r][n] = sum_k A[r][k] * Bcat[k][n],  then sigmoid.
//   A[r][k] (virtual): k<1024 -> x[r][k]; k>=1024 -> (t>0 ? x[r-1][k-1024] : 0)
//   Bcat[k][n]:        k<1024 -> W_w[k][n]; else V_w[k-1024][n]   (ld = 3*D)
// Tile 128x128x16, 256 threads, 8x8 per thread.
// ============================================================================
#define BM 128
#define BN 128
#define BK 16
#define TM 8
#define TN 8

__global__ __launch_bounds__(256) void fgemm_kernel(
    const float* __restrict__ x,
    const float* __restrict__ Ww,
    const float* __restrict__ Vw,
    const float* __restrict__ Vb)
{
    __shared__ float As[BK][BM];
    __shared__ float Bs[BK][BN];

    const int n0 = blockIdx.x * BN;
    const int r0 = blockIdx.y * BM;

    const int tid  = threadIdx.x;
    const int trow = tid >> 4;   // 0..15
    const int tcol = tid & 15;   // 0..15

    float acc[TM][TN];
    #pragma unroll
    for (int i = 0; i < TM; i++)
        #pragma unroll
        for (int j = 0; j < TN; j++) acc[i][j] = 0.0f;

    for (int k0 = 0; k0 < KCAT; k0 += BK) {
        // ---- load A tile (128 rows x 16 k), virtualized shifted-concat ----
        #pragma unroll
        for (int i = 0; i < 2; i++) {
            int q   = tid + i * 256;     // 0..511 float4 slots
            int row = q >> 2;            // 0..127
            int kk  = (q & 3) << 2;      // 0,4,8,12
            int r   = r0 + row;
            int k   = k0 + kk;
            float4 v;
            if (k < INDIM) {
                v = *reinterpret_cast<const float4*>(x + (size_t)r * INDIM + k);
            } else {
                int t = r & (SEQ - 1);
                if (t > 0)
                    v = *reinterpret_cast<const float4*>(x + (size_t)(r - 1) * INDIM + (k - INDIM));
                else
                    v = make_float4(0.f, 0.f, 0.f, 0.f);
            }
            As[kk + 0][row] = v.x;
            As[kk + 1][row] = v.y;
            As[kk + 2][row] = v.z;
            As[kk + 3][row] = v.w;
        }
        // ---- load B tile (16 k x 128 n) ----
        #pragma unroll
        for (int i = 0; i < 2; i++) {
            int q  = tid + i * 256;
            int kk = q >> 5;             // 0..15
            int n  = (q & 31) << 2;      // 0..124
            int k  = k0 + kk;
            const float* src = (k < INDIM)
                ? (Ww + (size_t)k * (3 * DDIM) + n0 + n)
                : (Vw + (size_t)(k - INDIM) * (3 * DDIM) + n0 + n);
            float4 v = *reinterpret_cast<const float4*>(src);
            *reinterpret_cast<float4*>(&Bs[kk][n]) = v;
        }
        __syncthreads();

        #pragma unroll
        for (int kk = 0; kk < BK; kk++) {
            float a[TM], b[TN];
            #pragma unroll
            for (int i = 0; i < TM; i++) a[i] = As[kk][trow * TM + i];
            #pragma unroll
            for (int j = 0; j < TN; j++) b[j] = Bs[kk][tcol * TN + j];
            #pragma unroll
            for (int i = 0; i < TM; i++)
                #pragma unroll
                for (int j = 0; j < TN; j++)
                    acc[i][j] += a[i] * b[j];
        }
        __syncthreads();
    }

    // epilogue: add bias, sigmoid, store f
    #pragma unroll
    for (int i = 0; i < TM; i++) {
        int r = r0 + trow * TM + i;
        #pragma unroll
        for (int j = 0; j < TN; j++) {
            int n = n0 + tcol * TN + j;
            float v = acc[i][j] + Vb[n];
            g_F[(size_t)r * DDIM + n] = sigmoidf_(v);
        }
    }
}

// ============================================================================
// Kernel 2: recurrence c_t = f_t * (c_{t-1} + 1) over S per (b,d) chain.
// Coalesced: consecutive threads = consecutive d.
// ============================================================================
__global__ __launch_bounds__(256) void recur_kernel()
{
    int idx = blockIdx.x * blockDim.x + threadIdx.x;   // 0..32767
    int b = idx >> 10;
    int d = idx & 1023;
    const float* p = g_F + (size_t)b * SEQ * DDIM + d;
    float c = 0.0f;
    #pragma unroll 8
    for (int t = 0; t < SEQ; t++) {
        c = p[(size_t)t * DDIM] * (c + 1.0f);
    }
    g_c[idx] = c;
}

// ============================================================================
// Kernel 3: o_pre at last timestep + h = c * sigmoid(o_pre).
//   o_pre[b][d] = x[b,S-1]·Ww[:,2D+d] + x[b,S-2]·Vw[:,2D+d] + Vb[2D+d]
// Warp = fixed b, consecutive d -> W loads coalesced, x broadcast.
// ============================================================================
__global__ __launch_bounds__(256) void oh_kernel(
    const float* __restrict__ x,
    const float* __restrict__ Ww,
    const float* __restrict__ Vw,
    const float* __restrict__ Vb)
{
    int idx = blockIdx.x * blockDim.x + threadIdx.x;   // 0..32767
    int b = idx >> 10;
    int d = idx & 1023;
    const float* xlast = x + ((size_t)b * SEQ + (SEQ - 1)) * INDIM;
    const float* xprev = xlast - INDIM;
    const float* wcol  = Ww + 2 * DDIM + d;
    const float* vcol  = Vw + 2 * DDIM + d;
    float acc = Vb[2 * DDIM + d];
    #pragma unroll 4
    for (int k = 0; k < INDIM; k++) {
        acc += xlast[k] * wcol[(size_t)k * (3 * DDIM)];
        acc += xprev[k] * vcol[(size_t)k * (3 * DDIM)];
    }
    g_h[idx] = g_c[idx] * sigmoidf_(acc);
}

// ============================================================================
// Kernel 4: MLP layers 0 and 1 (M=32, N=2048). relu(A @ W + b).
// Block: 64 cols x all 32 rows, K-tile 32. layer selects scratch buffers.
// ============================================================================
__global__ __launch_bounds__(256) void mlp_kernel(
    const float* __restrict__ W,
    const float* __restrict__ bias,
    int KDIM, int layer)
{
    const float* Ain = (layer == 0) ? g_h  : g_q0;
    float*       out = (layer == 0) ? g_q0 : g_q1;

    __shared__ float As[32][33];
    __shared__ float Bs[32][64];

    int n0   = blockIdx.x * 64;
    int tid  = threadIdx.x;
    int tcol = tid & 63;   // column within tile
    int trow = tid >> 6;   // 0..3 -> rows trow*8..trow*8+7

    float acc[8];
    #pragma unroll
    for (int i = 0; i < 8; i++) acc[i] = 0.0f;

    for (int k0 = 0; k0 < KDIM; k0 += 32) {
        #pragma unroll
        for (int i = 0; i < 4; i++) {
            int lin = tid + i * 256;
            int m = lin >> 5, kk = lin & 31;
            As[m][kk] = Ain[(size_t)m * KDIM + k0 + kk];
        }
        #pragma unroll
        for (int i = 0; i < 8; i++) {
            int lin = tid + i * 256;
            int kk = lin >> 6, n = lin & 63;
            Bs[kk][n] = W[(size_t)(k0 + kk) * MLPDIM + n0 + n];
        }
        __syncthreads();
        #pragma unroll
        for (int kk = 0; kk < 32; kk++) {
            float bv = Bs[kk][tcol];
            #pragma unroll
            for (int i = 0; i < 8; i++)
                acc[i] += As[trow * 8 + i][kk] * bv;
        }
        __syncthreads();
    }

    #pragma unroll
    for (int i = 0; i < 8; i++) {
        float v = acc[i] + bias[n0 + tcol];
        v = fmaxf(v, 0.0f);
        out[(size_t)(trow * 8 + i) * MLPDIM + n0 + tcol] = v;
    }
}

// ============================================================================
// Kernel 5: head. out[32][10] = q1 @ l2_w + l2_b. One warp per output element.
// ============================================================================
__global__ __launch_bounds__(256) void head_kernel(
    const float* __restrict__ W2,
    const float* __restrict__ b2,
    float* __restrict__ out)
{
    int warp = (blockIdx.x * blockDim.x + threadIdx.x) >> 5;
    int lane = threadIdx.x & 31;
    if (warp >= BATCH * NCLS) return;
    int m = warp / NCLS;
    int n = warp % NCLS;
    const float* a = g_q1 + (size_t)m * MLPDIM;
    float s = 0.0f;
    for (int k = lane; k < MLPDIM; k += 32)
        s += a[k] * W2[(size_t)k * NCLS + n];
    #pragma unroll
    for (int off = 16; off; off >>= 1)
        s += __shfl_xor_sync(0xffffffffu, s, off);
    if (lane == 0) out[warp] = s + b2[n];
}

// ============================================================================
extern "C" void kernel_launch(void* const* d_in, const int* in_sizes, int n_in,
                              void* d_out, int out_size)
{
    const float* x   = (const float*)d_in[0];
    const float* Ww  = (const float*)d_in[1];
    const float* Vw  = (const float*)d_in[2];
    const float* Vb  = (const float*)d_in[3];
    const float* l0w = (const float*)d_in[4];
    const float* l0b = (const float*)d_in[5];
    const float* l1w = (const float*)d_in[6];
    const float* l1b = (const float*)d_in[7];
    const float* l2w = (const float*)d_in[8];
    const float* l2b = (const float*)d_in[9];
    float* out = (float*)d_out;

    // 1. f = sigmoid(x@Wf + xprev@Vf + Vbf)   [dominant GEMM]
    dim3 grid1(DDIM / BN, BSROWS / BM);        // (8, 256)
    fgemm_kernel<<<grid1, 256>>>(x, Ww, Vw, Vb);

    // 2. recurrence -> c_last
    recur_kernel<<<(BATCH * DDIM) / 256, 256>>>();

    // 3. o at last timestep, h = c * o
    oh_kernel<<<(BATCH * DDIM) / 256, 256>>>(x, Ww, Vw, Vb);

    // 4. MLP
    mlp_kernel<<<MLPDIM / 64, 256>>>(l0w, l0b, DDIM,   0);
    mlp_kernel<<<MLPDIM / 64, 256>>>(l1w, l1b, MLPDIM, 1);

    // 5. head -> out [32,10]
    head_kernel<<<(BATCH * NCLS * 32 + 255) / 256, 256>>>(l2w, l2b, out);
}

// round 4
// speedup vs baseline: 1.9634x; 1.9634x over previous
#include <cuda_runtime.h>
#include <cuda_bf16.h>
#include <cstdint>
#include <math.h>

// Problem constants
#define BATCH   32
#define SEQ     1024
#define INDIM   1024
#define DDIM    1024
#define MLPDIM  2048
#define NCLS    10
#define BSROWS  (BATCH * SEQ)     // 32768
#define KCAT    (2 * INDIM)       // 2048

// GEMM tiling
#define BM 128
#define BN 128
#define BK 32
#define NKCH (KCAT / BK)          // 64 k-chunks
#define PIPE 3
// smem: 4 arrays (Ahi,Alo,Bhi,Blo), each 128 rows x 40 bf16 (32 data + 8 pad)
#define ROWSTRIDE 40
#define ARR_BYTES (BM * ROWSTRIDE * 2)     // 10240
#define STAGE_BYTES (4 * ARR_BYTES)        // 40960
#define SMEM_TOTAL (PIPE * STAGE_BYTES)    // 122880

// ---------------- scratch (device globals; zero-initialized at load) ----------------
__device__ __align__(16) __nv_bfloat16 g_ahi[(size_t)BSROWS * KCAT];  // 128 MB
__device__ __align__(16) __nv_bfloat16 g_alo[(size_t)BSROWS * KCAT];  // 128 MB
__device__ __align__(16) __nv_bfloat16 g_bhi[(size_t)DDIM * KCAT];    // [n][k] transposed
__device__ __align__(16) __nv_bfloat16 g_blo[(size_t)DDIM * KCAT];

__device__ float g_F[(size_t)BSROWS * DDIM];   // f = sigmoid(f_pre)
__device__ float g_c[BATCH * DDIM];
__device__ float g_h[BATCH * DDIM];
__device__ float g_q0[BATCH * MLPDIM];
__device__ float g_q1[BATCH * MLPDIM];

__device__ __forceinline__ float sigmoidf_(float v) {
    return 1.0f / (1.0f + expf(-v));
}

__device__ __forceinline__ uint32_t smem_u32(const void* p) {
    uint32_t a;
    asm("{ .reg .u64 t; cvta.to.shared.u64 t, %1; cvt.u32.u64 %0, t; }" : "=r"(a) : "l"(p));
    return a;
}
__device__ __forceinline__ void cpasync16(uint32_t dst, const void* gsrc) {
    asm volatile("cp.async.cg.shared.global [%0], [%1], 16;"
                 :: "r"(dst), "l"(__cvta_generic_to_global(gsrc)) : "memory");
}
__device__ __forceinline__ void cp_commit() {
    asm volatile("cp.async.commit_group;" ::: "memory");
}
template <int N>
__device__ __forceinline__ void cp_wait() {
    asm volatile("cp.async.wait_group %0;" :: "n"(N) : "memory");
}
__device__ __forceinline__ void mma_bf16(float* c, const uint32_t* a, const uint32_t* b) {
    asm volatile(
        "mma.sync.aligned.m16n8k16.row.col.f32.bf16.bf16.f32 "
        "{%0,%1,%2,%3}, {%4,%5,%6,%7}, {%8,%9}, {%0,%1,%2,%3};"
        : "+f"(c[0]), "+f"(c[1]), "+f"(c[2]), "+f"(c[3])
        : "r"(a[0]), "r"(a[1]), "r"(a[2]), "r"(a[3]), "r"(b[0]), "r"(b[1]));
}

// ---------------- convert x -> bf16 hi/lo A-cat scratch ----------------
// A[r][k]: k<1024 -> x[r][k]; k>=1024 -> x[r-1][k-1024] (t=0 rows stay zero)
__global__ __launch_bounds__(256) void convert_x_kernel(const float* __restrict__ x)
{
    size_t idx = (size_t)blockIdx.x * blockDim.x + threadIdx.x;  // BSROWS*128
    size_t r = idx >> 7;
    int j = (int)(idx & 127) * 8;

    const float4* src = reinterpret_cast<const float4*>(x + r * INDIM + j);
    float4 v0 = src[0], v1 = src[1];
    float vs[8] = {v0.x, v0.y, v0.z, v0.w, v1.x, v1.y, v1.z, v1.w};

    uint32_t hw[4], lw[4];
    #pragma unroll
    for (int i = 0; i < 4; i++) {
        __nv_bfloat16 h0 = __float2bfloat16(vs[2*i]);
        __nv_bfloat16 h1 = __float2bfloat16(vs[2*i+1]);
        __nv_bfloat16 l0 = __float2bfloat16(vs[2*i]   - __bfloat162float(h0));
        __nv_bfloat16 l1 = __float2bfloat16(vs[2*i+1] - __bfloat162float(h1));
        hw[i] = (uint32_t)__bfloat16_as_ushort(h0) | ((uint32_t)__bfloat16_as_ushort(h1) << 16);
        lw[i] = (uint32_t)__bfloat16_as_ushort(l0) | ((uint32_t)__bfloat16_as_ushort(l1) << 16);
    }
    uint4 hv = make_uint4(hw[0], hw[1], hw[2], hw[3]);
    uint4 lv = make_uint4(lw[0], lw[1], lw[2], lw[3]);

    reinterpret_cast<uint4*>(g_ahi)[(r * KCAT + j) >> 3] = hv;
    reinterpret_cast<uint4*>(g_alo)[(r * KCAT + j) >> 3] = lv;
    size_t r2 = r + 1;
    if ((r2 & (SEQ - 1)) != 0) {
        reinterpret_cast<uint4*>(g_ahi)[(r2 * KCAT + INDIM + j) >> 3] = hv;
        reinterpret_cast<uint4*>(g_alo)[(r2 * KCAT + INDIM + j) >> 3] = lv;
    }
}

// ---------------- convert weights: Bcat^T [n][k] bf16 hi/lo ----------------
// Bcat[k][n] = k<1024 ? Ww[k][n] : Vw[k-1024][n]   (first D columns = f gate)
__global__ __launch_bounds__(256) void convert_w_kernel(
    const float* __restrict__ Ww, const float* __restrict__ Vw)
{
    __shared__ float s[32][33];
    int kt = blockIdx.x;     // 0..63  (k tile of 32)
    int nt = blockIdx.y;     // 0..31  (n tile of 32)
    int k0 = kt * 32, n0 = nt * 32;
    int tid = threadIdx.x;

    const float* src = (k0 < INDIM) ? (Ww + (size_t)k0 * (3 * DDIM))
                                    : (Vw + (size_t)(k0 - INDIM) * (3 * DDIM));
    #pragma unroll
    for (int i = 0; i < 4; i++) {
        int lin = tid + i * 256;
        int kk = lin >> 5, nn = lin & 31;
        s[kk][nn] = src[(size_t)kk * (3 * DDIM) + n0 + nn];
    }
    __syncthreads();

    #pragma unroll
    for (int i = 0; i < 2; i++) {
        int lin = tid + i * 256;    // 512 u32 outputs
        int nn = lin >> 4;
        int kp = lin & 15;          // k-pair
        float a = s[kp * 2][nn], b = s[kp * 2 + 1][nn];
        __nv_bfloat16 h0 = __float2bfloat16(a);
        __nv_bfloat16 h1 = __float2bfloat16(b);
        __nv_bfloat16 l0 = __float2bfloat16(a - __bfloat162float(h0));
        __nv_bfloat16 l1 = __float2bfloat16(b - __bfloat162float(h1));
        size_t off = ((size_t)(n0 + nn) * KCAT + k0 + kp * 2) >> 1;
        reinterpret_cast<uint32_t*>(g_bhi)[off] =
            (uint32_t)__bfloat16_as_ushort(h0) | ((uint32_t)__bfloat16_as_ushort(h1) << 16);
        reinterpret_cast<uint32_t*>(g_blo)[off] =
            (uint32_t)__bfloat16_as_ushort(l0) | ((uint32_t)__bfloat16_as_ushort(l1) << 16);
    }
}

// ---------------- main GEMM: mma.sync bf16 3-pass split ----------------
// grid (8 n, 256 m), 256 threads = 8 warps (4 m x 2 n), warp tile 32x64
__global__ __launch_bounds__(256) void fgemm_mma_kernel(const float* __restrict__ Vb)
{
    extern __shared__ __align__(16) char smem[];
    const int tid = threadIdx.x;
    const int wid = tid >> 5, lane = tid & 31;
    const int mwarp = wid >> 1, nwarp = wid & 1;
    const int g = lane >> 2, t4 = lane & 3;

    const size_t r0 = (size_t)blockIdx.y * BM;
    const int n0 = blockIdx.x * BN;

    float c[2][8][4];
    #pragma unroll
    for (int mt = 0; mt < 2; mt++)
        #pragma unroll
        for (int nt = 0; nt < 8; nt++)
            #pragma unroll
            for (int i = 0; i < 4; i++) c[mt][nt][i] = 0.0f;

    // prefetch helper: stage s, k-chunk kc; 2048 16B chunks, 8 per thread
    auto prefetch = [&](int kc, int s) {
        const uint32_t sbase = smem_u32(smem) + (uint32_t)s * STAGE_BYTES;
        const int k0 = kc * BK;
        #pragma unroll
        for (int i = 0; i < 8; i++) {
            int cidx = tid + i * 256;
            int arr  = cidx >> 9;          // 0..3
            int rem  = cidx & 511;
            int row  = rem >> 2;
            int ch   = rem & 3;
            const __nv_bfloat16* gb;
            size_t grow;
            if (arr == 0)      { gb = g_ahi; grow = r0 + row; }
            else if (arr == 1) { gb = g_alo; grow = r0 + row; }
            else if (arr == 2) { gb = g_bhi; grow = (size_t)n0 + row; }
            else               { gb = g_blo; grow = (size_t)n0 + row; }
            const char* src = (const char*)(gb + grow * KCAT + k0) + ch * 16;
            uint32_t dst = sbase + (uint32_t)arr * ARR_BYTES + row * (ROWSTRIDE * 2) + ch * 16;
            cpasync16(dst, src);
        }
        cp_commit();
    };

    prefetch(0, 0);
    prefetch(1, 1);

    for (int kc = 0; kc < NKCH; kc++) {
        int s = kc % PIPE;
        cp_wait<1>();
        __syncthreads();

        // prefetch kc+2 into stage (kc+2)%PIPE (that stage's compute finished)
        if (kc + 2 < NKCH) prefetch(kc + 2, (kc + 2) % PIPE);
        else cp_commit();

        const __nv_bfloat16* sAhi = (const __nv_bfloat16*)(smem + (size_t)s * STAGE_BYTES);
        const __nv_bfloat16* sAlo = sAhi + BM * ROWSTRIDE;
        const __nv_bfloat16* sBhi = sAlo + BM * ROWSTRIDE;
        const __nv_bfloat16* sBlo = sBhi + BM * ROWSTRIDE;

        #pragma unroll
        for (int h = 0; h < 2; h++) {            // two k16 steps
            const int kb = h * 16 + t4 * 2;
            uint32_t aH[2][4], aL[2][4];
            #pragma unroll
            for (int mt = 0; mt < 2; mt++) {
                int rr = mwarp * 32 + mt * 16 + g;
                aH[mt][0] = *(const uint32_t*)(sAhi + rr * ROWSTRIDE + kb);
                aH[mt][1] = *(const uint32_t*)(sAhi + (rr + 8) * ROWSTRIDE + kb);
                aH[mt][2] = *(const uint32_t*)(sAhi + rr * ROWSTRIDE + kb + 8);
                aH[mt][3] = *(const uint32_t*)(sAhi + (rr + 8) * ROWSTRIDE + kb + 8);
                aL[mt][0] = *(const uint32_t*)(sAlo + rr * ROWSTRIDE + kb);
                aL[mt][1] = *(const uint32_t*)(sAlo + (rr + 8) * ROWSTRIDE + kb);
                aL[mt][2] = *(const uint32_t*)(sAlo + rr * ROWSTRIDE + kb + 8);
                aL[mt][3] = *(const uint32_t*)(sAlo + (rr + 8) * ROWSTRIDE + kb + 8);
            }
            uint32_t bH[8][2], bL[8][2];
            #pragma unroll
            for (int nt = 0; nt < 8; nt++) {
                int nn = nwarp * 64 + nt * 8 + g;
                bH[nt][0] = *(const uint32_t*)(sBhi + nn * ROWSTRIDE + kb);
                bH[nt][1] = *(const uint32_t*)(sBhi + nn * ROWSTRIDE + kb + 8);
                bL[nt][0] = *(const uint32_t*)(sBlo + nn * ROWSTRIDE + kb);
                bL[nt][1] = *(const uint32_t*)(sBlo + nn * ROWSTRIDE + kb + 8);
            }
            #pragma unroll
            for (int mt = 0; mt < 2; mt++)
                #pragma unroll
                for (int nt = 0; nt < 8; nt++) {
                    mma_bf16(c[mt][nt], aH[mt], bH[nt]);
                    mma_bf16(c[mt][nt], aH[mt], bL[nt]);
                    mma_bf16(c[mt][nt], aL[mt], bH[nt]);
                }
        }
        __syncthreads();
    }

    // epilogue: bias + sigmoid -> g_F
    #pragma unroll
    for (int mt = 0; mt < 2; mt++) {
        #pragma unroll
        for (int nt = 0; nt < 8; nt++) {
            size_t m = r0 + mwarp * 32 + mt * 16 + g;
            int n = n0 + nwarp * 64 + nt * 8 + t4 * 2;
            float b0 = Vb[n], b1 = Vb[n + 1];
            float2 v0, v1;
            v0.x = sigmoidf_(c[mt][nt][0] + b0);
            v0.y = sigmoidf_(c[mt][nt][1] + b1);
            v1.x = sigmoidf_(c[mt][nt][2] + b0);
            v1.y = sigmoidf_(c[mt][nt][3] + b1);
            *reinterpret_cast<float2*>(g_F + m * DDIM + n) = v0;
            *reinterpret_cast<float2*>(g_F + (m + 8) * DDIM + n) = v1;
        }
    }
}

// ---------------- recurrence ----------------
__global__ __launch_bounds__(256) void recur_kernel()
{
    int idx = blockIdx.x * blockDim.x + threadIdx.x;
    int b = idx >> 10;
    int d = idx & 1023;
    const float* p = g_F + (size_t)b * SEQ * DDIM + d;
    float c = 0.0f;
    #pragma unroll 8
    for (int t = 0; t < SEQ; t++)
        c = p[(size_t)t * DDIM] * (c + 1.0f);
    g_c[idx] = c;
}

// ---------------- o at last timestep + h ----------------
__global__ __launch_bounds__(256) void oh_kernel(
    const float* __restrict__ x,
    const float* __restrict__ Ww,
    const float* __restrict__ Vw,
    const float* __restrict__ Vb)
{
    int idx = blockIdx.x * blockDim.x + threadIdx.x;
    int b = idx >> 10;
    int d = idx & 1023;
    const float* xlast = x + ((size_t)b * SEQ + (SEQ - 1)) * INDIM;
    const float* xprev = xlast - INDIM;
    const float* wcol  = Ww + 2 * DDIM + d;
    const float* vcol  = Vw + 2 * DDIM + d;
    float acc = Vb[2 * DDIM + d];
    #pragma unroll 4
    for (int k = 0; k < INDIM; k++) {
        acc += xlast[k] * wcol[(size_t)k * (3 * DDIM)];
        acc += xprev[k] * vcol[(size_t)k * (3 * DDIM)];
    }
    g_h[idx] = g_c[idx] * sigmoidf_(acc);
}

// ---------------- MLP layers (M=32, N=2048) ----------------
__global__ __launch_bounds__(256) void mlp_kernel(
    const float* __restrict__ W,
    const float* __restrict__ bias,
    int KDIM, int layer)
{
    const float* Ain = (layer == 0) ? g_h  : g_q0;
    float*       out = (layer == 0) ? g_q0 : g_q1;

    __shared__ float As[32][33];
    __shared__ float Bs[32][33];

    int n0   = blockIdx.x * 32;
    int tid  = threadIdx.x;
    int tcol = tid & 31;
    int trow = tid >> 5;

    float acc[4] = {0.f, 0.f, 0.f, 0.f};

    for (int k0 = 0; k0 < KDIM; k0 += 32) {
        #pragma unroll
        for (int i = 0; i < 4; i++) {
            int lin = tid + i * 256;
            int m = lin >> 5, kk = lin & 31;
            As[m][kk] = Ain[(size_t)m * KDIM + k0 + kk];
            Bs[m][kk] = W[(size_t)(k0 + m) * MLPDIM + n0 + kk];
        }
        __syncthreads();
        #pragma unroll
        for (int kk = 0; kk < 32; kk++) {
            float bv = Bs[kk][tcol];
            #pragma unroll
            for (int i = 0; i < 4; i++)
                acc[i] += As[trow * 4 + i][kk] * bv;
        }
        __syncthreads();
    }
    #pragma unroll
    for (int i = 0; i < 4; i++) {
        float v = acc[i] + bias[n0 + tcol];
        out[(size_t)(trow * 4 + i) * MLPDIM + n0 + tcol] = fmaxf(v, 0.0f);
    }
}

// ---------------- head ----------------
__global__ __launch_bounds__(256) void head_kernel(
    const float* __restrict__ W2,
    const float* __restrict__ b2,
    float* __restrict__ out)
{
    int warp = (blockIdx.x * blockDim.x + threadIdx.x) >> 5;
    int lane = threadIdx.x & 31;
    if (warp >= BATCH * NCLS) return;
    int m = warp / NCLS;
    int n = warp % NCLS;
    const float* a = g_q1 + (size_t)m * MLPDIM;
    float s = 0.0f;
    for (int k = lane; k < MLPDIM; k += 32)
        s += a[k] * W2[(size_t)k * NCLS + n];
    #pragma unroll
    for (int off = 16; off; off >>= 1)
        s += __shfl_xor_sync(0xffffffffu, s, off);
    if (lane == 0) out[warp] = s + b2[n];
}

// ============================================================================
extern "C" void kernel_launch(void* const* d_in, const int* in_sizes, int n_in,
                              void* d_out, int out_size)
{
    const float* x   = (const float*)d_in[0];
    const float* Ww  = (const float*)d_in[1];
    const float* Vw  = (const float*)d_in[2];
    const float* Vb  = (const float*)d_in[3];
    const float* l0w = (const float*)d_in[4];
    const float* l0b = (const float*)d_in[5];
    const float* l1w = (const float*)d_in[6];
    const float* l1b = (const float*)d_in[7];
    const float* l2w = (const float*)d_in[8];
    const float* l2b = (const float*)d_in[9];
    float* out = (float*)d_out;

    cudaFuncSetAttribute(fgemm_mma_kernel,
                         cudaFuncAttributeMaxDynamicSharedMemorySize, SMEM_TOTAL);

    // 0. convert to bf16 hi/lo scratch
    convert_x_kernel<<<(BSROWS * 128) / 256, 256>>>(x);
    convert_w_kernel<<<dim3(KCAT / 32, DDIM / 32), 256>>>(Ww, Vw);

    // 1. f = sigmoid(x@Wf + xprev@Vf + b) via bf16-split mma.sync
    fgemm_mma_kernel<<<dim3(DDIM / BN, BSROWS / BM), 256, SMEM_TOTAL>>>(Vb);

    // 2. recurrence -> c_last
    recur_kernel<<<(BATCH * DDIM) / 256, 256>>>();

    // 3. o at last timestep, h = c * o
    oh_kernel<<<(BATCH * DDIM) / 256, 256>>>(x, Ww, Vw, Vb);

    // 4. MLP
    mlp_kernel<<<MLPDIM / 32, 256>>>(l0w, l0b, DDIM,   0);
    mlp_kernel<<<MLPDIM / 32, 256>>>(l1w, l1b, MLPDIM, 1);

    // 5. head
    head_kernel<<<(BATCH * NCLS * 32 + 255) / 256, 256>>>(l2w, l2b, out);
}

// round 8
// speedup vs baseline: 2.3494x; 1.1966x over previous
// R8: resubmission of the audited R4-design kernel (rounds 5-7 died to infra,
// never executed). No semantic changes vs R7 submission.
#include <cuda_runtime.h>
#include <cuda_bf16.h>
#include <cstdint>
#include <math.h>

// Problem constants
#define BATCH   32
#define SEQ     1024
#define INDIM   1024
#define DDIM    1024
#define MLPDIM  2048
#define NCLS    10
#define BSROWS  (BATCH * SEQ)     // 32768
#define KCAT    (2 * INDIM)       // 2048

// GEMM tiling
#define BM 128
#define BN 256
#define BK 32
#define NKCH (KCAT / BK)          // 64 k-chunks
#define XH   (INDIM / BK)         // 16 (chunks in first half)
#define PIPE 3
#define ROWSTRIDE 40              // bf16 per smem row (32 data + 8 pad), 80 bytes
#define A_ARR_BYTES (BM * ROWSTRIDE * 2)     // 10240
#define B_ARR_BYTES (BN * ROWSTRIDE * 2)     // 20480
#define STAGE_BYTES (2 * A_ARR_BYTES + 2 * B_ARR_BYTES)  // 61440
#define SMEM_TOTAL (PIPE * STAGE_BYTES)      // 184320

// recurrence segmentation
#define RSEG 8
#define SEGLEN (SEQ / RSEG)       // 128

// ---------------- scratch (device globals) ----------------
__device__ __align__(16) __nv_bfloat16 g_ahi[(size_t)BSROWS * INDIM];  // 64 MB
__device__ __align__(16) __nv_bfloat16 g_alo[(size_t)BSROWS * INDIM];  // 64 MB
__device__ __align__(16) __nv_bfloat16 g_bhi[(size_t)DDIM * KCAT];     // [n][k]
__device__ __align__(16) __nv_bfloat16 g_blo[(size_t)DDIM * KCAT];

__device__ float g_F[(size_t)BSROWS * DDIM];   // f = sigmoid(f_pre)
__device__ float g_segA[RSEG * BATCH * DDIM];
__device__ float g_segB[RSEG * BATCH * DDIM];
__device__ float g_c[BATCH * DDIM];
__device__ float g_h[BATCH * DDIM];
__device__ float g_q0[BATCH * MLPDIM];
__device__ float g_q1[BATCH * MLPDIM];

__device__ __forceinline__ float sigmoidf_(float v) {
    return 1.0f / (1.0f + expf(-v));
}
__device__ __forceinline__ uint32_t smem_u32(const void* p) {
    uint32_t a;
    asm("{ .reg .u64 t; cvta.to.shared.u64 t, %1; cvt.u32.u64 %0, t; }" : "=r"(a) : "l"(p));
    return a;
}
__device__ __forceinline__ void cpasync16z(uint32_t dst, const void* gsrc, uint32_t srcbytes) {
    asm volatile("cp.async.cg.shared.global [%0], [%1], 16, %2;"
                 :: "r"(dst), "l"(__cvta_generic_to_global(gsrc)), "r"(srcbytes) : "memory");
}
__device__ __forceinline__ void cp_commit() {
    asm volatile("cp.async.commit_group;" ::: "memory");
}
template <int N>
__device__ __forceinline__ void cp_wait() {
    asm volatile("cp.async.wait_group %0;" :: "n"(N) : "memory");
}
__device__ __forceinline__ void ldsm_x4(uint32_t* r, uint32_t addr) {
    asm volatile("ldmatrix.sync.aligned.m8n8.x4.shared.b16 {%0,%1,%2,%3}, [%4];"
                 : "=r"(r[0]), "=r"(r[1]), "=r"(r[2]), "=r"(r[3]) : "r"(addr));
}
__device__ __forceinline__ void mma_bf16(float* c, const uint32_t* a, const uint32_t* b) {
    asm volatile(
        "mma.sync.aligned.m16n8k16.row.col.f32.bf16.bf16.f32 "
        "{%0,%1,%2,%3}, {%4,%5,%6,%7}, {%8,%9}, {%0,%1,%2,%3};"
        : "+f"(c[0]), "+f"(c[1]), "+f"(c[2]), "+f"(c[3])
        : "r"(a[0]), "r"(a[1]), "r"(a[2]), "r"(a[3]), "r"(b[0]), "r"(b[1]));
}

// ---------------- convert x -> bf16 hi/lo [r][0:1024] ----------------
__global__ __launch_bounds__(256) void convert_x_kernel(const float* __restrict__ x)
{
    size_t idx = (size_t)blockIdx.x * blockDim.x + threadIdx.x;  // BSROWS*128
    size_t r = idx >> 7;
    int j = (int)(idx & 127) * 8;

    const float4* src = reinterpret_cast<const float4*>(x + r * INDIM + j);
    float4 v0 = src[0], v1 = src[1];
    float vs[8] = {v0.x, v0.y, v0.z, v0.w, v1.x, v1.y, v1.z, v1.w};

    uint32_t hw[4], lw[4];
    #pragma unroll
    for (int i = 0; i < 4; i++) {
        __nv_bfloat16 h0 = __float2bfloat16(vs[2*i]);
        __nv_bfloat16 h1 = __float2bfloat16(vs[2*i+1]);
        __nv_bfloat16 l0 = __float2bfloat16(vs[2*i]   - __bfloat162float(h0));
        __nv_bfloat16 l1 = __float2bfloat16(vs[2*i+1] - __bfloat162float(h1));
        hw[i] = (uint32_t)__bfloat16_as_ushort(h0) | ((uint32_t)__bfloat16_as_ushort(h1) << 16);
        lw[i] = (uint32_t)__bfloat16_as_ushort(l0) | ((uint32_t)__bfloat16_as_ushort(l1) << 16);
    }
    reinterpret_cast<uint4*>(g_ahi)[(r * INDIM + j) >> 3] = make_uint4(hw[0], hw[1], hw[2], hw[3]);
    reinterpret_cast<uint4*>(g_alo)[(r * INDIM + j) >> 3] = make_uint4(lw[0], lw[1], lw[2], lw[3]);
}

// ---------------- convert weights: Bcat^T [n][k] bf16 hi/lo ----------------
__global__ __launch_bounds__(256) void convert_w_kernel(
    const float* __restrict__ Ww, const float* __restrict__ Vw)
{
    __shared__ float s[32][33];
    int kt = blockIdx.x;     // 0..63
    int nt = blockIdx.y;     // 0..31
    int k0 = kt * 32, n0 = nt * 32;
    int tid = threadIdx.x;

    const float* src = (k0 < INDIM) ? (Ww + (size_t)k0 * (3 * DDIM))
                                    : (Vw + (size_t)(k0 - INDIM) * (3 * DDIM));
    #pragma unroll
    for (int i = 0; i < 4; i++) {
        int lin = tid + i * 256;
        int kk = lin >> 5, nn = lin & 31;
        s[kk][nn] = src[(size_t)kk * (3 * DDIM) + n0 + nn];
    }
    __syncthreads();

    #pragma unroll
    for (int i = 0; i < 2; i++) {
        int lin = tid + i * 256;
        int nn = lin >> 4;
        int kp = lin & 15;
        float a = s[kp * 2][nn], b = s[kp * 2 + 1][nn];
        __nv_bfloat16 h0 = __float2bfloat16(a);
        __nv_bfloat16 h1 = __float2bfloat16(b);
        __nv_bfloat16 l0 = __float2bfloat16(a - __bfloat162float(h0));
        __nv_bfloat16 l1 = __float2bfloat16(b - __bfloat162float(h1));
        size_t off = ((size_t)(n0 + nn) * KCAT + k0 + kp * 2) >> 1;
        reinterpret_cast<uint32_t*>(g_bhi)[off] =
            (uint32_t)__bfloat16_as_ushort(h0) | ((uint32_t)__bfloat16_as_ushort(h1) << 16);
        reinterpret_cast<uint32_t*>(g_blo)[off] =
            (uint32_t)__bfloat16_as_ushort(l0) | ((uint32_t)__bfloat16_as_ushort(l1) << 16);
    }
}

// ---------------- main GEMM: mma.sync bf16 3-pass split ----------------
// grid (4 n, 256 m), 512 threads = 16 warps (4 m x 4 n), warp tile 32x64
__global__ __launch_bounds__(512, 1) void fgemm_mma_kernel(const float* __restrict__ Vb)
{
    extern __shared__ __align__(16) char smem[];
    const uint32_t sbase = smem_u32(smem);
    const int tid = threadIdx.x;
    const int wid = tid >> 5, lane = tid & 31;
    const int mwarp = wid >> 2, nwarp = wid & 3;
    const int g = lane >> 2, t4 = lane & 3;

    const size_t r0 = (size_t)blockIdx.y * BM;
    const int n0 = blockIdx.x * BN;

    // ldmatrix per-lane byte offsets
    const uint32_t a_off = (((lane >> 3) & 1) * 8 + (lane & 7)) * 80 + (lane >> 4) * 16;
    const uint32_t b_off = (((lane >> 4) & 1) * 8 + (lane & 7)) * 80 + ((lane >> 3) & 1) * 16;

    float c[2][8][4];
    #pragma unroll
    for (int mt = 0; mt < 2; mt++)
        #pragma unroll
        for (int nt = 0; nt < 8; nt++)
            #pragma unroll
            for (int i = 0; i < 4; i++) c[mt][nt][i] = 0.0f;

    // prefetch: 3072 16B chunks per stage, 512 threads -> 6 each
    auto prefetch = [&](int kc, int s) {
        const uint32_t st = sbase + (uint32_t)s * STAGE_BYTES;
        #pragma unroll
        for (int i = 0; i < 6; i++) {
            int cidx = tid + i * 512;
            if (cidx < 1024) {
                // A: hi/lo, 128 rows x 4 chunks
                int hilo = cidx >> 9;
                int rem  = cidx & 511;
                int row  = rem >> 2;
                int ch   = rem & 3;
                uint32_t dst = st + (uint32_t)hilo * A_ARR_BYTES + row * 80 + ch * 16;
                const __nv_bfloat16* base = hilo ? g_alo : g_ahi;
                const void* src;
                uint32_t sz = 16;
                if (kc < XH) {
                    src = base + (r0 + row) * INDIM + kc * BK + ch * 8;
                } else {
                    bool z = (row == 0) && ((r0 & (SEQ - 1)) == 0);
                    src = z ? (const void*)base
                            : (const void*)(base + (r0 + row - 1) * INDIM + (kc - XH) * BK + ch * 8);
                    sz = z ? 0u : 16u;
                }
                cpasync16z(dst, src, sz);
            } else {
                // B: hi/lo, 256 rows x 4 chunks
                int cidx2 = cidx - 1024;
                int hilo = cidx2 >> 10;
                int rem  = cidx2 & 1023;
                int row  = rem >> 2;
                int ch   = rem & 3;
                uint32_t dst = st + 2 * A_ARR_BYTES + (uint32_t)hilo * B_ARR_BYTES + row * 80 + ch * 16;
                const __nv_bfloat16* base = hilo ? g_blo : g_bhi;
                cpasync16z(dst, base + (size_t)(n0 + row) * KCAT + kc * BK + ch * 8, 16);
            }
        }
        cp_commit();
    };

    prefetch(0, 0);
    prefetch(1, 1);

    for (int kc = 0; kc < NKCH; kc++) {
        int s = kc % PIPE;
        cp_wait<1>();
        __syncthreads();

        if (kc + 2 < NKCH) prefetch(kc + 2, (kc + 2) % PIPE);
        else cp_commit();

        const uint32_t sA_hi = sbase + (uint32_t)s * STAGE_BYTES;
        const uint32_t sA_lo = sA_hi + A_ARR_BYTES;
        const uint32_t sB_hi = sA_hi + 2 * A_ARR_BYTES;
        const uint32_t sB_lo = sB_hi + B_ARR_BYTES;

        #pragma unroll
        for (int h = 0; h < 2; h++) {
            uint32_t aH[2][4], aL[2][4];
            #pragma unroll
            for (int mt = 0; mt < 2; mt++) {
                uint32_t rb = (uint32_t)(mwarp * 32 + mt * 16) * 80 + h * 32;
                ldsm_x4(aH[mt], sA_hi + rb + a_off);
                ldsm_x4(aL[mt], sA_lo + rb + a_off);
            }
            #pragma unroll
            for (int p = 0; p < 4; p++) {
                uint32_t bh[4], bl[4];
                uint32_t nb = (uint32_t)(nwarp * 64 + p * 16) * 80 + h * 32;
                ldsm_x4(bh, sB_hi + nb + b_off);
                ldsm_x4(bl, sB_lo + nb + b_off);
                // pass Ah*Bh
                mma_bf16(c[0][2*p],   aH[0], bh);
                mma_bf16(c[0][2*p+1], aH[0], bh + 2);
                mma_bf16(c[1][2*p],   aH[1], bh);
                mma_bf16(c[1][2*p+1], aH[1], bh + 2);
                // pass Ah*Bl
                mma_bf16(c[0][2*p],   aH[0], bl);
                mma_bf16(c[0][2*p+1], aH[0], bl + 2);
                mma_bf16(c[1][2*p],   aH[1], bl);
                mma_bf16(c[1][2*p+1], aH[1], bl + 2);
                // pass Al*Bh
                mma_bf16(c[0][2*p],   aL[0], bh);
                mma_bf16(c[0][2*p+1], aL[0], bh + 2);
                mma_bf16(c[1][2*p],   aL[1], bh);
                mma_bf16(c[1][2*p+1], aL[1], bh + 2);
            }
        }
        __syncthreads();
    }

    // epilogue: bias + sigmoid -> g_F
    #pragma unroll
    for (int mt = 0; mt < 2; mt++) {
        #pragma unroll
        for (int nt = 0; nt < 8; nt++) {
            size_t m = r0 + mwarp * 32 + mt * 16 + g;
            int n = n0 + nwarp * 64 + nt * 8 + t4 * 2;
            float b0 = Vb[n], b1 = Vb[n + 1];
            float2 v0, v1;
            v0.x = sigmoidf_(c[mt][nt][0] + b0);
            v0.y = sigmoidf_(c[mt][nt][1] + b1);
            v1.x = sigmoidf_(c[mt][nt][2] + b0);
            v1.y = sigmoidf_(c[mt][nt][3] + b1);
            *reinterpret_cast<float2*>(g_F + m * DDIM + n) = v0;
            *reinterpret_cast<float2*>(g_F + (m + 8) * DDIM + n) = v1;
        }
    }
}

// ---------------- recurrence, segmented (affine composition) ----------------
__global__ __launch_bounds__(256) void recur_part_kernel()
{
    int gidx = blockIdx.x * blockDim.x + threadIdx.x;   // 0..262143
    int seg = gidx >> 15;
    int r   = gidx & 32767;
    int b = r >> 10;
    int d = r & 1023;
    const float* p = g_F + ((size_t)b * SEQ + seg * SEGLEN) * DDIM + d;
    float A = 1.0f, B = 0.0f;
    #pragma unroll 8
    for (int t = 0; t < SEGLEN; t++) {
        float f = p[(size_t)t * DDIM];
        A *= f;
        B = f * (B + 1.0f);
    }
    g_segA[gidx] = A;
    g_segB[gidx] = B;
}

__global__ __launch_bounds__(256) void recur_combine_kernel()
{
    int idx = blockIdx.x * blockDim.x + threadIdx.x;    // 0..32767
    float c = 0.0f;
    #pragma unroll
    for (int s = 0; s < RSEG; s++)
        c = g_segA[s * (BATCH * DDIM) + idx] * c + g_segB[s * (BATCH * DDIM) + idx];
    g_c[idx] = c;
}

// ---------------- o at last timestep + h ----------------
__global__ __launch_bounds__(256) void oh_kernel(
    const float* __restrict__ x,
    const float* __restrict__ Ww,
    const float* __restrict__ Vw,
    const float* __restrict__ Vb)
{
    int idx = blockIdx.x * blockDim.x + threadIdx.x;
    int b = idx >> 10;
    int d = idx & 1023;
    const float* xlast = x + ((size_t)b * SEQ + (SEQ - 1)) * INDIM;
    const float* xprev = xlast - INDIM;
    const float* wcol  = Ww + 2 * DDIM + d;
    const float* vcol  = Vw + 2 * DDIM + d;
    float acc = Vb[2 * DDIM + d];
    #pragma unroll 4
    for (int k = 0; k < INDIM; k++) {
        acc += xlast[k] * wcol[(size_t)k * (3 * DDIM)];
        acc += xprev[k] * vcol[(size_t)k * (3 * DDIM)];
    }
    g_h[idx] = g_c[idx] * sigmoidf_(acc);
}

// ---------------- MLP layers (M=32, N=2048) ----------------
__global__ __launch_bounds__(256) void mlp_kernel(
    const float* __restrict__ W,
    const float* __restrict__ bias,
    int KDIM, int layer)
{
    const float* Ain = (layer == 0) ? g_h  : g_q0;
    float*       out = (layer == 0) ? g_q0 : g_q1;

    __shared__ float As[32][33];
    __shared__ float Bs[32][33];

    int n0   = blockIdx.x * 32;
    int tid  = threadIdx.x;
    int tcol = tid & 31;
    int trow = tid >> 5;

    float acc[4] = {0.f, 0.f, 0.f, 0.f};

    for (int k0 = 0; k0 < KDIM; k0 += 32) {
        #pragma unroll
        for (int i = 0; i < 4; i++) {
            int lin = tid + i * 256;
            int m = lin >> 5, kk = lin & 31;
            As[m][kk] = Ain[(size_t)m * KDIM + k0 + kk];
            Bs[m][kk] = W[(size_t)(k0 + m) * MLPDIM + n0 + kk];
        }
        __syncthreads();
        #pragma unroll
        for (int kk = 0; kk < 32; kk++) {
            float bv = Bs[kk][tcol];
            #pragma unroll
            for (int i = 0; i < 4; i++)
                acc[i] += As[trow * 4 + i][kk] * bv;
        }
        __syncthreads();
    }
    #pragma unroll
    for (int i = 0; i < 4; i++) {
        float v = acc[i] + bias[n0 + tcol];
        out[(size_t)(trow * 4 + i) * MLPDIM + n0 + tcol] = fmaxf(v, 0.0f);
    }
}

// ---------------- head ----------------
__global__ __launch_bounds__(256) void head_kernel(
    const float* __restrict__ W2,
    const float* __restrict__ b2,
    float* __restrict__ out)
{
    int warp = (blockIdx.x * blockDim.x + threadIdx.x) >> 5;
    int lane = threadIdx.x & 31;
    if (warp >= BATCH * NCLS) return;
    int m = warp / NCLS;
    int n = warp % NCLS;
    const float* a = g_q1 + (size_t)m * MLPDIM;
    float s = 0.0f;
    for (int k = lane; k < MLPDIM; k += 32)
        s += a[k] * W2[(size_t)k * NCLS + n];
    #pragma unroll
    for (int off = 16; off; off >>= 1)
        s += __shfl_xor_sync(0xffffffffu, s, off);
    if (lane == 0) out[warp] = s + b2[n];
}

// ============================================================================
extern "C" void kernel_launch(void* const* d_in, const int* in_sizes, int n_in,
                              void* d_out, int out_size)
{
    const float* x   = (const float*)d_in[0];
    const float* Ww  = (const float*)d_in[1];
    const float* Vw  = (const float*)d_in[2];
    const float* Vb  = (const float*)d_in[3];
    const float* l0w = (const float*)d_in[4];
    const float* l0b = (const float*)d_in[5];
    const float* l1w = (const float*)d_in[6];
    const float* l1b = (const float*)d_in[7];
    const float* l2w = (const float*)d_in[8];
    const float* l2b = (const float*)d_in[9];
    float* out = (float*)d_out;

    cudaFuncSetAttribute(fgemm_mma_kernel,
                         cudaFuncAttributeMaxDynamicSharedMemorySize, SMEM_TOTAL);

    // 0. convert to bf16 hi/lo scratch
    convert_x_kernel<<<(BSROWS * 128) / 256, 256>>>(x);
    convert_w_kernel<<<dim3(KCAT / 32, DDIM / 32), 256>>>(Ww, Vw);

    // 1. f = sigmoid(x@Wf + xprev@Vf + b) via bf16-split mma.sync
    fgemm_mma_kernel<<<dim3(DDIM / BN, BSROWS / BM), 512, SMEM_TOTAL>>>(Vb);

    // 2. recurrence -> c_last (segmented)
    recur_part_kernel<<<(RSEG * BATCH * DDIM) / 256, 256>>>();
    recur_combine_kernel<<<(BATCH * DDIM) / 256, 256>>>();

    // 3. o at last timestep, h = c * o
    oh_kernel<<<(BATCH * DDIM) / 256, 256>>>(x, Ww, Vw, Vb);

    // 4. MLP
    mlp_kernel<<<MLPDIM / 32, 256>>>(l0w, l0b, DDIM,   0);
    mlp_kernel<<<MLPDIM / 32, 256>>>(l1w, l1b, MLPDIM, 1);

    // 5. head
    head_kernel<<<(BATCH * NCLS * 32 + 255) / 256, 256>>>(l2w, l2b, out);
}

// round 10
// speedup vs baseline: 2.5269x; 1.0755x over previous
// R10: resubmission of the audited R9 kernel (R9 died to infra, never ran).
// fgemm: 2 CTAs/SM (BN=128, 256 thr, PIPE=2), one __syncthreads per k-chunk.
#include <cuda_runtime.h>
#include <cuda_bf16.h>
#include <cstdint>
#include <math.h>

// Problem constants
#define BATCH   32
#define SEQ     1024
#define INDIM   1024
#define DDIM    1024
#define MLPDIM  2048
#define NCLS    10
#define BSROWS  (BATCH * SEQ)     // 32768
#define KCAT    (2 * INDIM)       // 2048

// GEMM tiling
#define BM 128
#define BN 128
#define BK 32
#define NKCH (KCAT / BK)          // 64 k-chunks
#define XH   (INDIM / BK)         // 16 (chunks in first half)
#define PIPE 2
#define ROWSTRIDE 40              // bf16 per smem row (32 data + 8 pad), 80 bytes
#define ARR_BYTES (128 * ROWSTRIDE * 2)      // 10240 (A and B both 128 rows)
#define STAGE_BYTES (4 * ARR_BYTES)          // 40960: Ahi, Alo, Bhi, Blo
#define SMEM_TOTAL (PIPE * STAGE_BYTES)      // 81920 -> 2 CTAs/SM

// recurrence segmentation
#define RSEG 8
#define SEGLEN (SEQ / RSEG)       // 128

// ---------------- scratch (device globals) ----------------
__device__ __align__(16) __nv_bfloat16 g_ahi[(size_t)BSROWS * INDIM];  // 64 MB
__device__ __align__(16) __nv_bfloat16 g_alo[(size_t)BSROWS * INDIM];  // 64 MB
__device__ __align__(16) __nv_bfloat16 g_bhi[(size_t)DDIM * KCAT];     // [n][k]
__device__ __align__(16) __nv_bfloat16 g_blo[(size_t)DDIM * KCAT];

__device__ float g_F[(size_t)BSROWS * DDIM];   // f = sigmoid(f_pre)
__device__ float g_segA[RSEG * BATCH * DDIM];
__device__ float g_segB[RSEG * BATCH * DDIM];
__device__ float g_c[BATCH * DDIM];
__device__ float g_h[BATCH * DDIM];
__device__ float g_q0[BATCH * MLPDIM];
__device__ float g_q1[BATCH * MLPDIM];

__device__ __forceinline__ float sigmoidf_(float v) {
    return 1.0f / (1.0f + expf(-v));
}
__device__ __forceinline__ uint32_t smem_u32(const void* p) {
    uint32_t a;
    asm("{ .reg .u64 t; cvta.to.shared.u64 t, %1; cvt.u32.u64 %0, t; }" : "=r"(a) : "l"(p));
    return a;
}
__device__ __forceinline__ void cpasync16z(uint32_t dst, const void* gsrc, uint32_t srcbytes) {
    asm volatile("cp.async.cg.shared.global [%0], [%1], 16, %2;"
                 :: "r"(dst), "l"(__cvta_generic_to_global(gsrc)), "r"(srcbytes) : "memory");
}
__device__ __forceinline__ void cp_commit() {
    asm volatile("cp.async.commit_group;" ::: "memory");
}
template <int N>
__device__ __forceinline__ void cp_wait() {
    asm volatile("cp.async.wait_group %0;" :: "n"(N) : "memory");
}
__device__ __forceinline__ void ldsm_x4(uint32_t* r, uint32_t addr) {
    asm volatile("ldmatrix.sync.aligned.m8n8.x4.shared.b16 {%0,%1,%2,%3}, [%4];"
                 : "=r"(r[0]), "=r"(r[1]), "=r"(r[2]), "=r"(r[3]) : "r"(addr));
}
__device__ __forceinline__ void mma_bf16(float* c, const uint32_t* a, const uint32_t* b) {
    asm volatile(
        "mma.sync.aligned.m16n8k16.row.col.f32.bf16.bf16.f32 "
        "{%0,%1,%2,%3}, {%4,%5,%6,%7}, {%8,%9}, {%0,%1,%2,%3};"
        : "+f"(c[0]), "+f"(c[1]), "+f"(c[2]), "+f"(c[3])
        : "r"(a[0]), "r"(a[1]), "r"(a[2]), "r"(a[3]), "r"(b[0]), "r"(b[1]));
}

// ---------------- convert x -> bf16 hi/lo [r][0:1024] ----------------
__global__ __launch_bounds__(256) void convert_x_kernel(const float* __restrict__ x)
{
    size_t idx = (size_t)blockIdx.x * blockDim.x + threadIdx.x;  // BSROWS*128
    size_t r = idx >> 7;
    int j = (int)(idx & 127) * 8;

    const float4* src = reinterpret_cast<const float4*>(x + r * INDIM + j);
    float4 v0 = src[0], v1 = src[1];
    float vs[8] = {v0.x, v0.y, v0.z, v0.w, v1.x, v1.y, v1.z, v1.w};

    uint32_t hw[4], lw[4];
    #pragma unroll
    for (int i = 0; i < 4; i++) {
        __nv_bfloat16 h0 = __float2bfloat16(vs[2*i]);
        __nv_bfloat16 h1 = __float2bfloat16(vs[2*i+1]);
        __nv_bfloat16 l0 = __float2bfloat16(vs[2*i]   - __bfloat162float(h0));
        __nv_bfloat16 l1 = __float2bfloat16(vs[2*i+1] - __bfloat162float(h1));
        hw[i] = (uint32_t)__bfloat16_as_ushort(h0) | ((uint32_t)__bfloat16_as_ushort(h1) << 16);
        lw[i] = (uint32_t)__bfloat16_as_ushort(l0) | ((uint32_t)__bfloat16_as_ushort(l1) << 16);
    }
    reinterpret_cast<uint4*>(g_ahi)[(r * INDIM + j) >> 3] = make_uint4(hw[0], hw[1], hw[2], hw[3]);
    reinterpret_cast<uint4*>(g_alo)[(r * INDIM + j) >> 3] = make_uint4(lw[0], lw[1], lw[2], lw[3]);
}

// ---------------- convert weights: Bcat^T [n][k] bf16 hi/lo ----------------
__global__ __launch_bounds__(256) void convert_w_kernel(
    const float* __restrict__ Ww, const float* __restrict__ Vw)
{
    __shared__ float s[32][33];
    int kt = blockIdx.x;     // 0..63
    int nt = blockIdx.y;     // 0..31
    int k0 = kt * 32, n0 = nt * 32;
    int tid = threadIdx.x;

    const float* src = (k0 < INDIM) ? (Ww + (size_t)k0 * (3 * DDIM))
                                    : (Vw + (size_t)(k0 - INDIM) * (3 * DDIM));
    #pragma unroll
    for (int i = 0; i < 4; i++) {
        int lin = tid + i * 256;
        int kk = lin >> 5, nn = lin & 31;
        s[kk][nn] = src[(size_t)kk * (3 * DDIM) + n0 + nn];
    }
    __syncthreads();

    #pragma unroll
    for (int i = 0; i < 2; i++) {
        int lin = tid + i * 256;
        int nn = lin >> 4;
        int kp = lin & 15;
        float a = s[kp * 2][nn], b = s[kp * 2 + 1][nn];
        __nv_bfloat16 h0 = __float2bfloat16(a);
        __nv_bfloat16 h1 = __float2bfloat16(b);
        __nv_bfloat16 l0 = __float2bfloat16(a - __bfloat162float(h0));
        __nv_bfloat16 l1 = __float2bfloat16(b - __bfloat162float(h1));
        size_t off = ((size_t)(n0 + nn) * KCAT + k0 + kp * 2) >> 1;
        reinterpret_cast<uint32_t*>(g_bhi)[off] =
            (uint32_t)__bfloat16_as_ushort(h0) | ((uint32_t)__bfloat16_as_ushort(h1) << 16);
        reinterpret_cast<uint32_t*>(g_blo)[off] =
            (uint32_t)__bfloat16_as_ushort(l0) | ((uint32_t)__bfloat16_as_ushort(l1) << 16);
    }
}

// ---------------- main GEMM: mma.sync bf16 3-pass split ----------------
// grid (8 n, 256 m), 256 threads = 8 warps (4 m x 2 n), warp tile 32x64
// 2 CTAs/SM; PIPE=2; one __syncthreads per k-chunk.
__global__ __launch_bounds__(256, 2) void fgemm_mma_kernel(const float* __restrict__ Vb)
{
    extern __shared__ __align__(16) char smem[];
    const uint32_t sbase = smem_u32(smem);
    const int tid = threadIdx.x;
    const int wid = tid >> 5, lane = tid & 31;
    const int mwarp = wid >> 1, nwarp = wid & 1;
    const int g = lane >> 2, t4 = lane & 3;

    const size_t r0 = (size_t)blockIdx.y * BM;
    const int n0 = blockIdx.x * BN;

    // ldmatrix per-lane byte offsets (80B row stride; conflict-free)
    const uint32_t a_off = (((lane >> 3) & 1) * 8 + (lane & 7)) * 80 + (lane >> 4) * 16;
    const uint32_t b_off = (((lane >> 4) & 1) * 8 + (lane & 7)) * 80 + ((lane >> 3) & 1) * 16;

    float c[2][8][4];
    #pragma unroll
    for (int mt = 0; mt < 2; mt++)
        #pragma unroll
        for (int nt = 0; nt < 8; nt++)
            #pragma unroll
            for (int i = 0; i < 4; i++) c[mt][nt][i] = 0.0f;

    // prefetch: 2048 16B chunks per stage, 256 threads -> 8 each
    auto prefetch = [&](int kc, int s) {
        const uint32_t st = sbase + (uint32_t)s * STAGE_BYTES;
        #pragma unroll
        for (int i = 0; i < 8; i++) {
            int cidx = tid + i * 256;
            if (cidx < 1024) {
                // A: hi/lo, 128 rows x 4 chunks
                int hilo = cidx >> 9;
                int rem  = cidx & 511;
                int row  = rem >> 2;
                int ch   = rem & 3;
                uint32_t dst = st + (uint32_t)hilo * ARR_BYTES + row * 80 + ch * 16;
                const __nv_bfloat16* base = hilo ? g_alo : g_ahi;
                const void* src;
                uint32_t sz = 16;
                if (kc < XH) {
                    src = base + (r0 + row) * INDIM + kc * BK + ch * 8;
                } else {
                    bool z = (row == 0) && ((r0 & (SEQ - 1)) == 0);
                    src = z ? (const void*)base
                            : (const void*)(base + (r0 + row - 1) * INDIM + (kc - XH) * BK + ch * 8);
                    sz = z ? 0u : 16u;
                }
                cpasync16z(dst, src, sz);
            } else {
                // B: hi/lo, 128 rows x 4 chunks
                int cidx2 = cidx - 1024;
                int hilo = cidx2 >> 9;
                int rem  = cidx2 & 511;
                int row  = rem >> 2;
                int ch   = rem & 3;
                uint32_t dst = st + (uint32_t)(2 + hilo) * ARR_BYTES + row * 80 + ch * 16;
                const __nv_bfloat16* base = hilo ? g_blo : g_bhi;
                cpasync16z(dst, base + (size_t)(n0 + row) * KCAT + kc * BK + ch * 8, 16);
            }
        }
        cp_commit();
    };

    prefetch(0, 0);

    for (int kc = 0; kc < NKCH; kc++) {
        int s = kc & 1;
        cp_wait<0>();
        __syncthreads();
        // safe: stage (kc+1)&1 was last read at iteration kc-1; the barrier
        // above proves all warps have left it.
        if (kc + 1 < NKCH) prefetch(kc + 1, s ^ 1);

        const uint32_t sA_hi = sbase + (uint32_t)s * STAGE_BYTES;
        const uint32_t sA_lo = sA_hi + ARR_BYTES;
        const uint32_t sB_hi = sA_hi + 2 * ARR_BYTES;
        const uint32_t sB_lo = sA_hi + 3 * ARR_BYTES;

        #pragma unroll
        for (int h = 0; h < 2; h++) {
            uint32_t aH[2][4], aL[2][4];
            #pragma unroll
            for (int mt = 0; mt < 2; mt++) {
                uint32_t rb = (uint32_t)(mwarp * 32 + mt * 16) * 80 + h * 32;
                ldsm_x4(aH[mt], sA_hi + rb + a_off);
                ldsm_x4(aL[mt], sA_lo + rb + a_off);
            }
            #pragma unroll
            for (int p = 0; p < 4; p++) {
                uint32_t bh[4], bl[4];
                uint32_t nb = (uint32_t)(nwarp * 64 + p * 16) * 80 + h * 32;
                ldsm_x4(bh, sB_hi + nb + b_off);
                ldsm_x4(bl, sB_lo + nb + b_off);
                // pass Ah*Bh
                mma_bf16(c[0][2*p],   aH[0], bh);
                mma_bf16(c[0][2*p+1], aH[0], bh + 2);
                mma_bf16(c[1][2*p],   aH[1], bh);
                mma_bf16(c[1][2*p+1], aH[1], bh + 2);
                // pass Ah*Bl
                mma_bf16(c[0][2*p],   aH[0], bl);
                mma_bf16(c[0][2*p+1], aH[0], bl + 2);
                mma_bf16(c[1][2*p],   aH[1], bl);
                mma_bf16(c[1][2*p+1], aH[1], bl + 2);
                // pass Al*Bh
                mma_bf16(c[0][2*p],   aL[0], bh);
                mma_bf16(c[0][2*p+1], aL[0], bh + 2);
                mma_bf16(c[1][2*p],   aL[1], bh);
                mma_bf16(c[1][2*p+1], aL[1], bh + 2);
            }
        }
    }

    // epilogue: bias + sigmoid -> g_F
    #pragma unroll
    for (int mt = 0; mt < 2; mt++) {
        #pragma unroll
        for (int nt = 0; nt < 8; nt++) {
            size_t m = r0 + mwarp * 32 + mt * 16 + g;
            int n = n0 + nwarp * 64 + nt * 8 + t4 * 2;
            float b0 = Vb[n], b1 = Vb[n + 1];
            float2 v0, v1;
            v0.x = sigmoidf_(c[mt][nt][0] + b0);
            v0.y = sigmoidf_(c[mt][nt][1] + b1);
            v1.x = sigmoidf_(c[mt][nt][2] + b0);
            v1.y = sigmoidf_(c[mt][nt][3] + b1);
            *reinterpret_cast<float2*>(g_F + m * DDIM + n) = v0;
            *reinterpret_cast<float2*>(g_F + (m + 8) * DDIM + n) = v1;
        }
    }
}

// ---------------- recurrence, segmented (affine composition) ----------------
__global__ __launch_bounds__(256) void recur_part_kernel()
{
    int gidx = blockIdx.x * blockDim.x + threadIdx.x;   // 0..262143
    int seg = gidx >> 15;
    int r   = gidx & 32767;
    int b = r >> 10;
    int d = r & 1023;
    const float* p = g_F + ((size_t)b * SEQ + seg * SEGLEN) * DDIM + d;
    float A = 1.0f, B = 0.0f;
    #pragma unroll 8
    for (int t = 0; t < SEGLEN; t++) {
        float f = p[(size_t)t * DDIM];
        A *= f;
        B = f * (B + 1.0f);
    }
    g_segA[gidx] = A;
    g_segB[gidx] = B;
}

__global__ __launch_bounds__(256) void recur_combine_kernel()
{
    int idx = blockIdx.x * blockDim.x + threadIdx.x;    // 0..32767
    float c = 0.0f;
    #pragma unroll
    for (int s = 0; s < RSEG; s++)
        c = g_segA[s * (BATCH * DDIM) + idx] * c + g_segB[s * (BATCH * DDIM) + idx];
    g_c[idx] = c;
}

// ---------------- o at last timestep + h ----------------
__global__ __launch_bounds__(256) void oh_kernel(
    const float* __restrict__ x,
    const float* __restrict__ Ww,
    const float* __restrict__ Vw,
    const float* __restrict__ Vb)
{
    int idx = blockIdx.x * blockDim.x + threadIdx.x;
    int b = idx >> 10;
    int d = idx & 1023;
    const float* xlast = x + ((size_t)b * SEQ + (SEQ - 1)) * INDIM;
    const float* xprev = xlast - INDIM;
    const float* wcol  = Ww + 2 * DDIM + d;
    const float* vcol  = Vw + 2 * DDIM + d;
    float acc = Vb[2 * DDIM + d];
    #pragma unroll 4
    for (int k = 0; k < INDIM; k++) {
        acc += xlast[k] * wcol[(size_t)k * (3 * DDIM)];
        acc += xprev[k] * vcol[(size_t)k * (3 * DDIM)];
    }
    g_h[idx] = g_c[idx] * sigmoidf_(acc);
}

// ---------------- MLP layers (M=32, N=2048) ----------------
__global__ __launch_bounds__(256) void mlp_kernel(
    const float* __restrict__ W,
    const float* __restrict__ bias,
    int KDIM, int layer)
{
    const float* Ain = (layer == 0) ? g_h  : g_q0;
    float*       out = (layer == 0) ? g_q0 : g_q1;

    __shared__ float As[32][33];
    __shared__ float Bs[32][33];

    int n0   = blockIdx.x * 32;
    int tid  = threadIdx.x;
    int tcol = tid & 31;
    int trow = tid >> 5;

    float acc[4] = {0.f, 0.f, 0.f, 0.f};

    for (int k0 = 0; k0 < KDIM; k0 += 32) {
        #pragma unroll
        for (int i = 0; i < 4; i++) {
            int lin = tid + i * 256;
            int m = lin >> 5, kk = lin & 31;
            As[m][kk] = Ain[(size_t)m * KDIM + k0 + kk];
            Bs[m][kk] = W[(size_t)(k0 + m) * MLPDIM + n0 + kk];
        }
        __syncthreads();
        #pragma unroll
        for (int kk = 0; kk < 32; kk++) {
            float bv = Bs[kk][tcol];
            #pragma unroll
            for (int i = 0; i < 4; i++)
                acc[i] += As[trow * 4 + i][kk] * bv;
        }
        __syncthreads();
    }
    #pragma unroll
    for (int i = 0; i < 4; i++) {
        float v = acc[i] + bias[n0 + tcol];
        out[(size_t)(trow * 4 + i) * MLPDIM + n0 + tcol] = fmaxf(v, 0.0f);
    }
}

// ---------------- head ----------------
__global__ __launch_bounds__(256) void head_kernel(
    const float* __restrict__ W2,
    const float* __restrict__ b2,
    float* __restrict__ out)
{
    int warp = (blockIdx.x * blockDim.x + threadIdx.x) >> 5;
    int lane = threadIdx.x & 31;
    if (warp >= BATCH * NCLS) return;
    int m = warp / NCLS;
    int n = warp % NCLS;
    const float* a = g_q1 + (size_t)m * MLPDIM;
    float s = 0.0f;
    for (int k = lane; k < MLPDIM; k += 32)
        s += a[k] * W2[(size_t)k * NCLS + n];
    #pragma unroll
    for (int off = 16; off; off >>= 1)
        s += __shfl_xor_sync(0xffffffffu, s, off);
    if (lane == 0) out[warp] = s + b2[n];
}

// ============================================================================
extern "C" void kernel_launch(void* const* d_in, const int* in_sizes, int n_in,
                              void* d_out, int out_size)
{
    const float* x   = (const float*)d_in[0];
    const float* Ww  = (const float*)d_in[1];
    const float* Vw  = (const float*)d_in[2];
    const float* Vb  = (const float*)d_in[3];
    const float* l0w = (const float*)d_in[4];
    const float* l0b = (const float*)d_in[5];
    const float* l1w = (const float*)d_in[6];
    const float* l1b = (const float*)d_in[7];
    const float* l2w = (const float*)d_in[8];
    const float* l2b = (const float*)d_in[9];
    float* out = (float*)d_out;

    cudaFuncSetAttribute(fgemm_mma_kernel,
                         cudaFuncAttributeMaxDynamicSharedMemorySize, SMEM_TOTAL);

    // 0. convert to bf16 hi/lo scratch
    convert_x_kernel<<<(BSROWS * 128) / 256, 256>>>(x);
    convert_w_kernel<<<dim3(KCAT / 32, DDIM / 32), 256>>>(Ww, Vw);

    // 1. f = sigmoid(x@Wf + xprev@Vf + b) via bf16-split mma.sync
    fgemm_mma_kernel<<<dim3(DDIM / BN, BSROWS / BM), 256, SMEM_TOTAL>>>(Vb);

    // 2. recurrence -> c_last (segmented)
    recur_part_kernel<<<(RSEG * BATCH * DDIM) / 256, 256>>>();
    recur_combine_kernel<<<(BATCH * DDIM) / 256, 256>>>();

    // 3. o at last timestep, h = c * o
    oh_kernel<<<(BATCH * DDIM) / 256, 256>>>(x, Ww, Vw, Vb);

    // 4. MLP
    mlp_kernel<<<MLPDIM / 32, 256>>>(l0w, l0b, DDIM,   0);
    mlp_kernel<<<MLPDIM / 32, 256>>>(l1w, l1b, MLPDIM, 1);

    // 5. head
    head_kernel<<<(BATCH * NCLS * 32 + 255) / 256, 256>>>(l2w, l2b, out);
}